// round 14
// baseline (speedup 1.0000x reference)
#include <cuda_runtime.h>
#include <cuda_fp16.h>
#include <math_constants.h>

#define S_N   8192
#define SRC   768
#define DK    128
#define DV    64
#define KSPLIT 4
#define NIT   (S_N / KSPLIT / 64)   /* 32 key tiles per CTA */

typedef unsigned long long ull;
typedef unsigned int u32;

// ---------------- scratch (no allocations allowed) ----------------
__device__ __half g_Qf[S_N * DK];   // Q * log2e/sqrt(dk), fp16
__device__ __half g_Kf[S_N * DK];   // K, fp16
__device__ float g_vs[S_N];         // scalar V per key
__device__ float g_pl[KSPLIT * S_N], g_pa[KSPLIT * S_N];  // split partials
__device__ float g_x2sum;

// ---------------- helpers ------------------------------------------
__device__ __forceinline__ u32 smem_u32(const void* p) {
    u32 a; asm("{ .reg .u64 t; cvta.to.shared.u64 t, %1; cvt.u32.u64 %0, t; }" : "=r"(a) : "l"(p));
    return a;
}
__device__ __forceinline__ void ldsm_x4(u32& r0, u32& r1, u32& r2, u32& r3, u32 addr) {
    asm volatile("ldmatrix.sync.aligned.m8n8.x4.shared.b16 {%0,%1,%2,%3}, [%4];"
                 : "=r"(r0), "=r"(r1), "=r"(r2), "=r"(r3) : "r"(addr));
}
// f16-accumulator HMMA (2x tensor rate, half the C regs)
__device__ __forceinline__ void mma16816h(u32& d0, u32& d1,
                                          u32 a0, u32 a1, u32 a2, u32 a3,
                                          u32 b0, u32 b1) {
    asm volatile("mma.sync.aligned.m16n8k16.row.col.f16.f16.f16.f16 "
                 "{%0,%1},{%2,%3,%4,%5},{%6,%7},{%0,%1};"
                 : "+r"(d0), "+r"(d1)
                 : "r"(a0), "r"(a1), "r"(a2), "r"(a3), "r"(b0), "r"(b1));
}
__device__ __forceinline__ u32 ex2h2(u32 x) {
    u32 y; asm("ex2.approx.f16x2 %0, %1;" : "=r"(y) : "r"(x)); return y;
}
__device__ __forceinline__ u32 hadd2u(u32 a, u32 b) {
    u32 d; asm("add.f16x2 %0, %1, %2;" : "=r"(d) : "r"(a), "r"(b)); return d;
}
__device__ __forceinline__ u32 hmul2u(u32 a, u32 b) {
    u32 d; asm("mul.f16x2 %0, %1, %2;" : "=r"(d) : "r"(a), "r"(b)); return d;
}
__device__ __forceinline__ u32 hfma2u(u32 a, u32 b, u32 c) {
    u32 d; asm("fma.rn.f16x2 %0, %1, %2, %3;" : "=r"(d) : "r"(a), "r"(b), "r"(c)); return d;
}
__device__ __forceinline__ uint4 cvt8h(float4 a, float4 b) {
    __half2 h0 = __floats2half2_rn(a.x, a.y);
    __half2 h1 = __floats2half2_rn(a.z, a.w);
    __half2 h2 = __floats2half2_rn(b.x, b.y);
    __half2 h3 = __floats2half2_rn(b.z, b.w);
    uint4 u;
    u.x = *reinterpret_cast<u32*>(&h0);
    u.y = *reinterpret_cast<u32*>(&h1);
    u.z = *reinterpret_cast<u32*>(&h2);
    u.w = *reinterpret_cast<u32*>(&h3);
    return u;
}
__device__ __forceinline__ void cpa16(u32 dst, const void* src) {
    asm volatile("cp.async.cg.shared.global [%0], [%1], 16;" :: "r"(dst), "l"(src));
}
__device__ __forceinline__ void cpa4(u32 dst, const void* src) {
    asm volatile("cp.async.ca.shared.global [%0], [%1], 4;" :: "r"(dst), "l"(src));
}
__device__ __forceinline__ void cpa_commit() {
    asm volatile("cp.async.commit_group;" ::: "memory");
}
template <int N>
__device__ __forceinline__ void cpa_wait() {
    asm volatile("cp.async.wait_group %0;" :: "n"(N) : "memory");
}

// log2(e) / sqrt(128): folded into Q so softmax uses raw EX2, no max needed
#define CFOLD 0.12751743f

extern __shared__ char smem_raw[];

// ---------------- kernel 1: zero the sum flag ----------------------
__global__ void prep_kernel() {
    if (threadIdx.x == 0) g_x2sum = 0.0f;
}

// ---------------- kernel 2: Q/K projections on HMMA (f16 acc) ------
// Y[8192,128] = X[8192,768] @ W[128,768]^T, fp16 out (Q pre-scaled).
// CTA: 64 rows x 128 cols, K chunks of 64, 256 threads, 2 CTAs/SM.
// The K branch computes wvo = w_out @ w_v in-CTA (from L2), plus
// v_s = x2 @ wvo and sum(x2) fused into the staging loads.
#define PCH   12              /* 768 / 64 chunks */
#define OFF_XS  0             /* __half Xs[2][64][64]  = 16384 */
#define OFF_WS  16384         /* __half Ws[2][128][64] = 32768 */
#define OFF_WVS 49152         /* float wvs[768] = 3072 */
#define SMEM_PROJ 52224

__global__ void __launch_bounds__(256, 2)
proj_kernel(const float* __restrict__ x1, const float* __restrict__ x2,
            const float* __restrict__ wq, const float* __restrict__ wk,
            const float* __restrict__ w_v, const float* __restrict__ w_out) {
    const bool isQ = (blockIdx.y == 0);
    const float* X = isQ ? x1 : x2;
    const float* W = isQ ? wq : wk;
    __half* Y = isQ ? g_Qf : g_Kf;

    float* wvs = reinterpret_cast<float*>(smem_raw + OFF_WVS);

    const int tid = threadIdx.x, lane = tid & 31, w = tid >> 5;
    const int qg = w & 1;         // 32-row group (rows 0..63)
    const int nh = w >> 1;        // 32-col group (cols 0..127)
    const int r0 = blockIdx.x * 64;

    if (!isQ) {
        // wvo in-CTA: 3 columns per thread, w_v rows broadcast via L2
        #pragma unroll
        for (int i = 0; i < 3; i++) {
            int c = tid + i * 256;
            float acc = 0.0f;
            #pragma unroll 8
            for (int j = 0; j < DV; j++)
                acc = fmaf(w_out[j], w_v[j * SRC + c], acc);
            wvs[c] = acc;
        }
    }
    __syncthreads();

    // staging: X 512 uint4 slots (2/thread), W 1024 slots (4/thread)
    int xrow[2], xch[2], wrow[4], wch[4];
    #pragma unroll
    for (int i = 0; i < 2; i++) {
        int idx = tid + i * 256;
        xrow[i] = idx >> 3;
        xch[i]  = idx & 7;
    }
    #pragma unroll
    for (int i = 0; i < 4; i++) {
        int idx = tid + i * 256;
        wrow[i] = idx >> 3;
        wch[i]  = idx & 7;
    }

    float vsacc[2] = {0.0f, 0.0f};
    float xsum = 0.0f;

    uint4 pX[2], pW[4];
    auto load_regs = [&](int kk) {
        #pragma unroll
        for (int i = 0; i < 2; i++) {
            const float* sx = &X[(size_t)(r0 + xrow[i]) * SRC + kk + xch[i] * 8];
            float4 a = *reinterpret_cast<const float4*>(sx);
            float4 b = *reinterpret_cast<const float4*>(sx + 4);
            if (!isQ) {
                const float* wv = &wvs[kk + xch[i] * 8];
                vsacc[i] = fmaf(a.x, wv[0], vsacc[i]);
                vsacc[i] = fmaf(a.y, wv[1], vsacc[i]);
                vsacc[i] = fmaf(a.z, wv[2], vsacc[i]);
                vsacc[i] = fmaf(a.w, wv[3], vsacc[i]);
                vsacc[i] = fmaf(b.x, wv[4], vsacc[i]);
                vsacc[i] = fmaf(b.y, wv[5], vsacc[i]);
                vsacc[i] = fmaf(b.z, wv[6], vsacc[i]);
                vsacc[i] = fmaf(b.w, wv[7], vsacc[i]);
                xsum += (a.x + a.y) + (a.z + a.w) + (b.x + b.y) + (b.z + b.w);
            }
            pX[i] = cvt8h(a, b);
        }
        #pragma unroll
        for (int i = 0; i < 4; i++) {
            const float* sw = &W[(size_t)wrow[i] * SRC + kk + wch[i] * 8];
            pW[i] = cvt8h(*reinterpret_cast<const float4*>(sw),
                          *reinterpret_cast<const float4*>(sw + 4));
        }
    };
    auto store_smem = [&](int buf) {
        char* xb = smem_raw + OFF_XS + buf * 8192;
        char* wb = smem_raw + OFF_WS + buf * 16384;
        #pragma unroll
        for (int i = 0; i < 2; i++) {
            u32 dst = (u32)(xrow[i] * 128) + (u32)((xch[i] ^ (xrow[i] & 7)) << 4);
            *reinterpret_cast<uint4*>(xb + dst) = pX[i];
        }
        #pragma unroll
        for (int i = 0; i < 4; i++) {
            u32 dst = (u32)(wrow[i] * 128) + (u32)((wch[i] ^ (wrow[i] & 7)) << 4);
            *reinterpret_cast<uint4*>(wb + dst) = pW[i];
        }
    };

    u32 c2[2][4][2];
    #pragma unroll
    for (int mt = 0; mt < 2; mt++)
        #pragma unroll
        for (int j = 0; j < 4; j++) {
            c2[mt][j][0] = 0u;
            c2[mt][j][1] = 0u;
        }

    const u32 sX = smem_u32(smem_raw) + OFF_XS;
    const u32 sW = smem_u32(smem_raw) + OFF_WS;
    const int rbA = qg * 32 + (lane & 7) + (lane & 8);
    const int kbitA = lane >> 4;
    const int rbB = nh * 32 + (lane & 7) + ((lane & 16) >> 1);
    const int kbitB = (lane >> 3) & 1;

    load_regs(0);
    for (int cidx = 0; cidx < PCH; cidx++) {
        const int buf = cidx & 1;
        store_smem(buf);
        __syncthreads();
        if (cidx + 1 < PCH) load_regs((cidx + 1) * 64);

        const u32 xb = sX + buf * 8192;
        const u32 wb = sW + buf * 16384;
        #pragma unroll
        for (int ks = 0; ks < 4; ks++) {
            u32 A0[4], A1[4];
            int chA = ks * 2 + kbitA;
            {
                int r = rbA;
                ldsm_x4(A0[0], A0[1], A0[2], A0[3], xb + r * 128 + ((chA ^ (r & 7)) << 4));
            }
            {
                int r = rbA + 16;
                ldsm_x4(A1[0], A1[1], A1[2], A1[3], xb + r * 128 + ((chA ^ (r & 7)) << 4));
            }
            int chB = ks * 2 + kbitB;
            #pragma unroll
            for (int nt = 0; nt < 2; nt++) {
                u32 b[4];
                int r = rbB + nt * 16;
                ldsm_x4(b[0], b[1], b[2], b[3], wb + r * 128 + ((chB ^ (r & 7)) << 4));
                mma16816h(c2[0][nt*2+0][0], c2[0][nt*2+0][1],
                          A0[0], A0[1], A0[2], A0[3], b[0], b[1]);
                mma16816h(c2[0][nt*2+1][0], c2[0][nt*2+1][1],
                          A0[0], A0[1], A0[2], A0[3], b[2], b[3]);
                mma16816h(c2[1][nt*2+0][0], c2[1][nt*2+0][1],
                          A1[0], A1[1], A1[2], A1[3], b[0], b[1]);
                mma16816h(c2[1][nt*2+1][0], c2[1][nt*2+1][1],
                          A1[0], A1[1], A1[2], A1[3], b[2], b[3]);
            }
        }
        __syncthreads();
    }

    if (!isQ) {
        #pragma unroll
        for (int m = 1; m < 8; m <<= 1) {
            vsacc[0] += __shfl_xor_sync(0xffffffffu, vsacc[0], m);
            vsacc[1] += __shfl_xor_sync(0xffffffffu, vsacc[1], m);
            xsum     += __shfl_xor_sync(0xffffffffu, xsum, m);
        }
        if ((lane & 7) == 0) {
            g_vs[r0 + xrow[0]] = vsacc[0];
            g_vs[r0 + xrow[1]] = vsacc[1];
            atomicAdd(&g_x2sum, xsum);
        }
    }

    // epilogue: f16 accumulators stored directly (Q scaled in f16x2)
    __half2 sc2 = __float2half2_rn(isQ ? CFOLD : 1.0f);
    const u32 scu = *reinterpret_cast<u32*>(&sc2);
    #pragma unroll
    for (int mt = 0; mt < 2; mt++) {
        int row = r0 + qg * 32 + mt * 16 + (lane >> 2);
        #pragma unroll
        for (int j = 0; j < 4; j++) {
            int col = nh * 32 + j * 8 + (lane & 3) * 2;
            u32 lo = isQ ? hmul2u(c2[mt][j][0], scu) : c2[mt][j][0];
            u32 hi = isQ ? hmul2u(c2[mt][j][1], scu) : c2[mt][j][1];
            *reinterpret_cast<u32*>(&Y[(size_t)row * DK + col]) = lo;
            *reinterpret_cast<u32*>(&Y[(size_t)(row + 8) * DK + col]) = hi;
        }
    }
}

// ---------------- kernel 3: HMMA flash attention, f16 accumulators --
// CTA: 128 queries x 64-key tiles, 8 warps (warp = 32q x 32k).
// grid (64, KSPLIT). cp.async 3-stage K ring, 1 barrier/iter.
#define OFF_KS   32768         /* __half Ks[3][64][128] */
#define OFF_VSB  81920         /* float vsb[3][64] */
#define OFF_RL   82688         /* float rl[2][128] */
#define OFF_RA   83712         /* float ra[2][128] */
#define SMEM_FLASH 84736

__global__ void __launch_bounds__(256, 2) flash_kernel() {
    float* vsb = reinterpret_cast<float*>(smem_raw + OFF_VSB);
    float* rl  = reinterpret_cast<float*>(smem_raw + OFF_RL);
    float* ra  = reinterpret_cast<float*>(smem_raw + OFF_RA);

    const int tid = threadIdx.x, lane = tid & 31, w = tid >> 5;
    const int q0 = blockIdx.x * 128;
    const int k0 = blockIdx.y * (S_N / KSPLIT);
    const int kh = w >> 2;       // key half within tile (0/1)
    const int qg = w & 3;        // 32-query group
    const u32 sbase = smem_u32(smem_raw);

    const int krow = tid >> 4, kch = tid & 15;

    auto issue_tile = [&](int it) {
        const int slot = it % 3;
        const int t0 = k0 + it * 64;
        #pragma unroll
        for (int i = 0; i < 4; i++) {
            int row = krow + i * 16;
            u32 dst = sbase + OFF_KS + slot * 16384 +
                      (u32)(row * 256) + (u32)((kch ^ (row & 7)) << 4);
            cpa16(dst, g_Kf + (size_t)(t0 + row) * DK + kch * 8);
        }
        if (tid < 64)
            cpa4(sbase + OFF_VSB + slot * 256 + tid * 4, &g_vs[t0 + tid]);
        cpa_commit();
    };

    issue_tile(0);
    issue_tile(1);

    // stage Q (XOR-swizzled)
    #pragma unroll
    for (int i = 0; i < 8; i++) {
        int idx = tid + i * 256;
        int row = idx >> 4, ch = idx & 15;
        u32 dst = (u32)(row * 256) + (u32)((ch ^ (row & 7)) << 4);
        *reinterpret_cast<uint4*>(smem_raw + dst) =
            *reinterpret_cast<const uint4*>(g_Qf + (size_t)(q0 + row) * DK + ch * 8);
    }
    __syncthreads();

    // A fragments: register-resident for the whole CTA lifetime
    u32 A[2][8][4];
    {
        int rb = qg * 32 + (lane & 7) + (lane & 8);
        int kbit = lane >> 4;
        #pragma unroll
        for (int mt = 0; mt < 2; mt++) {
            int row = rb + mt * 16;
            #pragma unroll
            for (int ks = 0; ks < 8; ks++) {
                int ch = ks * 2 + kbit;
                ldsm_x4(A[mt][ks][0], A[mt][ks][1], A[mt][ks][2], A[mt][ks][3],
                        sbase + row * 256 + ((ch ^ (row & 7)) << 4));
            }
        }
    }

    const u32 sK = sbase + OFF_KS;
    const int rB0 = kh * 32 + (lane & 7) + ((lane & 16) >> 1);
    const int kbitB = (lane >> 3) & 1;

    float l_[4] = {0, 0, 0, 0}, a_[4] = {0, 0, 0, 0};

    for (int it = 0; it < NIT; it++) {
        const int slot = it % 3;
        if (it + 1 < NIT) cpa_wait<1>(); else cpa_wait<0>();
        __syncthreads();
        if (it + 2 < NIT) issue_tile(it + 2);

        // ---- QK^T on tensor cores, fp16 accumulators ----
        u32 c2[2][4][2];
        #pragma unroll
        for (int mt = 0; mt < 2; mt++)
            #pragma unroll
            for (int j = 0; j < 4; j++) {
                c2[mt][j][0] = 0u;
                c2[mt][j][1] = 0u;
            }

        const u32 kb = sK + slot * 16384;
        #pragma unroll
        for (int ks = 0; ks < 8; ks++) {
            u32 b[8];
            int ch = ks * 2 + kbitB;
            {
                int row = rB0;
                ldsm_x4(b[0], b[1], b[2], b[3],
                        kb + row * 256 + ((ch ^ (row & 7)) << 4));
            }
            {
                int row = rB0 + 16;
                ldsm_x4(b[4], b[5], b[6], b[7],
                        kb + row * 256 + ((ch ^ (row & 7)) << 4));
            }
            #pragma unroll
            for (int mt = 0; mt < 2; mt++) {
                mma16816h(c2[mt][0][0], c2[mt][0][1],
                          A[mt][ks][0], A[mt][ks][1], A[mt][ks][2], A[mt][ks][3], b[0], b[1]);
                mma16816h(c2[mt][1][0], c2[mt][1][1],
                          A[mt][ks][0], A[mt][ks][1], A[mt][ks][2], A[mt][ks][3], b[2], b[3]);
                mma16816h(c2[mt][2][0], c2[mt][2][1],
                          A[mt][ks][0], A[mt][ks][1], A[mt][ks][2], A[mt][ks][3], b[4], b[5]);
                mma16816h(c2[mt][3][0], c2[mt][3][1],
                          A[mt][ks][0], A[mt][ks][1], A[mt][ks][2], A[mt][ks][3], b[6], b[7]);
            }
        }

        // ---- softmax accumulate: p = 2^s, f16x2 fma against packed v ----
        const float* vv = vsb + slot * 64 + kh * 32 + (lane & 3) * 2;
        u32 vs2h[4];
        #pragma unroll
        for (int j = 0; j < 4; j++) {
            float2 v2 = *reinterpret_cast<const float2*>(vv + j * 8);
            __half2 h = __floats2half2_rn(v2.x, v2.y);
            vs2h[j] = *reinterpret_cast<u32*>(&h);
        }
        u32 lh2[4] = {0u, 0u, 0u, 0u};
        u32 ah2[4] = {0u, 0u, 0u, 0u};
        #pragma unroll
        for (int j = 0; j < 4; j++) {
            #pragma unroll
            for (int mt = 0; mt < 2; mt++) {
                #pragma unroll
                for (int rr = 0; rr < 2; rr++) {
                    int r = mt * 2 + rr;
                    u32 p2 = ex2h2(c2[mt][j][rr]);
                    lh2[r] = hadd2u(lh2[r], p2);
                    ah2[r] = hfma2u(p2, vs2h[j], ah2[r]);
                }
            }
        }
        #pragma unroll
        for (int r = 0; r < 4; r++) {
            __half2 lh = *reinterpret_cast<__half2*>(&lh2[r]);
            l_[r] += __low2float(lh) + __high2float(lh);
            __half2 ah = *reinterpret_cast<__half2*>(&ah2[r]);
            a_[r] += __low2float(ah) + __high2float(ah);
        }
    }

    // quad reduce (lanes sharing a row are lane^1, lane^2)
    #pragma unroll
    for (int r = 0; r < 4; r++) {
        l_[r] += __shfl_xor_sync(0xffffffffu, l_[r], 1);
        l_[r] += __shfl_xor_sync(0xffffffffu, l_[r], 2);
        a_[r] += __shfl_xor_sync(0xffffffffu, a_[r], 1);
        a_[r] += __shfl_xor_sync(0xffffffffu, a_[r], 2);
    }
    __syncthreads();
    if ((lane & 3) == 0) {
        int gid = lane >> 2;
        #pragma unroll
        for (int r = 0; r < 4; r++) {
            int mt = r >> 1, rr = r & 1;
            int qrow = qg * 32 + mt * 16 + gid + rr * 8;
            rl[kh * 128 + qrow] = l_[r];
            ra[kh * 128 + qrow] = a_[r];
        }
    }
    __syncthreads();
    if (tid < 128) {
        int r = blockIdx.y * S_N + q0 + tid;
        g_pl[r] = rl[tid] + rl[128 + tid];
        g_pa[r] = ra[tid] + ra[128 + tid];
    }
}

// ---------------- kernel 4: fused combine + gate -------------------
// Block = 8 exact rows (1536 float4), 256 threads x 6 independent float4.
__global__ void __launch_bounds__(256) gate_kernel(const float* __restrict__ x1,
                                                   float* __restrict__ y) {
    __shared__ float gs[8];
    const int b = blockIdx.x, tid = threadIdx.x;
    if (tid < 8) {
        int r = 8 * b + tid;
        float g = 0.0f;
        if (g_x2sum != 0.0f) {
            float L = 0.0f, A = 0.0f;
            #pragma unroll
            for (int s = 0; s < KSPLIT; s++) {
                L += g_pl[s * S_N + r];
                A += g_pa[s * S_N + r];
            }
            g = A / L;
        }
        gs[tid] = g;
    }
    __syncthreads();
    const float4* xin = reinterpret_cast<const float4*>(x1) + (size_t)b * 1536;
    float4* yo = reinterpret_cast<float4*>(y) + (size_t)b * 1536;
    float4 v[6];
    #pragma unroll
    for (int k = 0; k < 6; k++) v[k] = xin[tid + k * 256];
    #pragma unroll
    for (int k = 0; k < 6; k++) {
        float f = 1.0f - gs[(tid + k * 256) / 192];
        v[k].x *= f; v[k].y *= f; v[k].z *= f; v[k].w *= f;
        yo[tid + k * 256] = v[k];
    }
}

// ---------------- launch ------------------------------------------
extern "C" void kernel_launch(void* const* d_in, const int* in_sizes, int n_in,
                              void* d_out, int out_size) {
    const float* x1 = (const float*)d_in[0];
    const float* x2 = (const float*)d_in[1];
    const float* wq = (const float*)d_in[2];
    const float* wk = (const float*)d_in[3];
    const float* wv = (const float*)d_in[4];
    const float* wo = (const float*)d_in[5];
    float* y = (float*)d_out;

    cudaFuncSetAttribute(flash_kernel, cudaFuncAttributeMaxDynamicSharedMemorySize,
                         SMEM_FLASH);
    cudaFuncSetAttribute(proj_kernel, cudaFuncAttributeMaxDynamicSharedMemorySize,
                         SMEM_PROJ);

    prep_kernel<<<1, 32>>>();
    proj_kernel<<<dim3(S_N / 64, 2), 256, SMEM_PROJ>>>(x1, x2, wq, wk, wv, wo);
    flash_kernel<<<dim3(S_N / 128, KSPLIT), 256, SMEM_FLASH>>>();
    gate_kernel<<<S_N / 8, 256>>>(x1, y);
}

// round 15
// speedup vs baseline: 1.0477x; 1.0477x over previous
#include <cuda_runtime.h>
#include <cuda_fp16.h>
#include <math_constants.h>

#define S_N   8192
#define SRC   768
#define DK    128
#define DV    64
#define KSPLIT 4
#define NIT   (S_N / KSPLIT / 64)   /* 32 key tiles per CTA */

typedef unsigned long long ull;
typedef unsigned int u32;

// ---------------- scratch (no allocations allowed) ----------------
__device__ __half g_Qf[S_N * DK];   // Q * log2e/sqrt(dk), fp16
__device__ __half g_Kf[S_N * DK];   // K, fp16
__device__ float g_vs[S_N];         // scalar V per key
__device__ float g_pl[KSPLIT * S_N], g_pa[KSPLIT * S_N];  // split partials
__device__ float g_wvo[SRC];        // w_output @ w_v
__device__ float g_x2sum;

// ---------------- helpers ------------------------------------------
__device__ __forceinline__ u32 smem_u32(const void* p) {
    u32 a; asm("{ .reg .u64 t; cvta.to.shared.u64 t, %1; cvt.u32.u64 %0, t; }" : "=r"(a) : "l"(p));
    return a;
}
__device__ __forceinline__ void ldsm_x4(u32& r0, u32& r1, u32& r2, u32& r3, u32 addr) {
    asm volatile("ldmatrix.sync.aligned.m8n8.x4.shared.b16 {%0,%1,%2,%3}, [%4];"
                 : "=r"(r0), "=r"(r1), "=r"(r2), "=r"(r3) : "r"(addr));
}
// f32-accumulator HMMA (projection kernel)
__device__ __forceinline__ void mma16816(float& d0, float& d1, float& d2, float& d3,
                                         u32 a0, u32 a1, u32 a2, u32 a3,
                                         u32 b0, u32 b1) {
    asm volatile("mma.sync.aligned.m16n8k16.row.col.f32.f16.f16.f32 "
                 "{%0,%1,%2,%3},{%4,%5,%6,%7},{%8,%9},{%0,%1,%2,%3};"
                 : "+f"(d0), "+f"(d1), "+f"(d2), "+f"(d3)
                 : "r"(a0), "r"(a1), "r"(a2), "r"(a3), "r"(b0), "r"(b1));
}
// f16-accumulator HMMA (flash kernel: 2x tensor rate, half the C regs)
__device__ __forceinline__ void mma16816h(u32& d0, u32& d1,
                                          u32 a0, u32 a1, u32 a2, u32 a3,
                                          u32 b0, u32 b1) {
    asm volatile("mma.sync.aligned.m16n8k16.row.col.f16.f16.f16.f16 "
                 "{%0,%1},{%2,%3,%4,%5},{%6,%7},{%0,%1};"
                 : "+r"(d0), "+r"(d1)
                 : "r"(a0), "r"(a1), "r"(a2), "r"(a3), "r"(b0), "r"(b1));
}
__device__ __forceinline__ u32 ex2h2(u32 x) {
    u32 y; asm("ex2.approx.f16x2 %0, %1;" : "=r"(y) : "r"(x)); return y;
}
__device__ __forceinline__ u32 hadd2u(u32 a, u32 b) {
    u32 d; asm("add.f16x2 %0, %1, %2;" : "=r"(d) : "r"(a), "r"(b)); return d;
}
__device__ __forceinline__ u32 hfma2u(u32 a, u32 b, u32 c) {
    u32 d; asm("fma.rn.f16x2 %0, %1, %2, %3;" : "=r"(d) : "r"(a), "r"(b), "r"(c)); return d;
}
__device__ __forceinline__ uint4 cvt8h(float4 a, float4 b) {
    __half2 h0 = __floats2half2_rn(a.x, a.y);
    __half2 h1 = __floats2half2_rn(a.z, a.w);
    __half2 h2 = __floats2half2_rn(b.x, b.y);
    __half2 h3 = __floats2half2_rn(b.z, b.w);
    uint4 u;
    u.x = *reinterpret_cast<u32*>(&h0);
    u.y = *reinterpret_cast<u32*>(&h1);
    u.z = *reinterpret_cast<u32*>(&h2);
    u.w = *reinterpret_cast<u32*>(&h3);
    return u;
}
__device__ __forceinline__ void cpa16(u32 dst, const void* src) {
    asm volatile("cp.async.cg.shared.global [%0], [%1], 16;" :: "r"(dst), "l"(src));
}
__device__ __forceinline__ void cpa4(u32 dst, const void* src) {
    asm volatile("cp.async.ca.shared.global [%0], [%1], 4;" :: "r"(dst), "l"(src));
}
__device__ __forceinline__ void cpa_commit() {
    asm volatile("cp.async.commit_group;" ::: "memory");
}
template <int N>
__device__ __forceinline__ void cpa_wait() {
    asm volatile("cp.async.wait_group %0;" :: "n"(N) : "memory");
}

// log2(e) / sqrt(128): folded into Q so softmax uses raw EX2, no max needed
#define CFOLD 0.12751743f

extern __shared__ char smem_raw[];

// ---------------- kernel 1: wvo = w_output @ w_v; zero flag --------
__global__ void prep_kernel(const float* __restrict__ w_v,
                            const float* __restrict__ w_out) {
    int c = threadIdx.x;
    if (c == 0) g_x2sum = 0.0f;
    if (c < SRC) {
        float acc = 0.0f;
        #pragma unroll
        for (int j = 0; j < DV; j++) acc += w_out[j] * w_v[j * SRC + c];
        g_wvo[c] = acc;
    }
}

// ---------------- kernel 2: Q/K projections on HMMA + fused vscalar --
// Y[8192,128] = X[8192,768] @ W[128,768]^T, fp16 out (Q pre-scaled).
// CTA: 64 rows x 128 cols, K chunks of 64, 256 threads, 2 CTAs/SM.
#define PCH   12              /* 768 / 64 chunks */
#define OFF_XS  0             /* __half Xs[2][64][64]  = 16384 */
#define OFF_WS  16384         /* __half Ws[2][128][64] = 32768 */
#define OFF_WVS 49152         /* float wvs[768] = 3072 */
#define SMEM_PROJ 52224

__global__ void __launch_bounds__(256, 2)
proj_kernel(const float* __restrict__ x1, const float* __restrict__ x2,
            const float* __restrict__ wq, const float* __restrict__ wk) {
    const bool isQ = (blockIdx.y == 0);
    const float* X = isQ ? x1 : x2;
    const float* W = isQ ? wq : wk;
    __half* Y = isQ ? g_Qf : g_Kf;

    float* wvs = reinterpret_cast<float*>(smem_raw + OFF_WVS);

    const int tid = threadIdx.x, lane = tid & 31, w = tid >> 5;
    const int qg = w & 1;         // 32-row group (rows 0..63)
    const int nh = w >> 1;        // 32-col group (cols 0..127)
    const int r0 = blockIdx.x * 64;

    if (!isQ) {
        for (int i = tid; i < SRC; i += 256) wvs[i] = g_wvo[i];
    }
    __syncthreads();

    // staging: X 512 uint4 slots (2/thread), W 1024 slots (4/thread)
    int xrow[2], xch[2], wrow[4], wch[4];
    #pragma unroll
    for (int i = 0; i < 2; i++) {
        int idx = tid + i * 256;
        xrow[i] = idx >> 3;
        xch[i]  = idx & 7;
    }
    #pragma unroll
    for (int i = 0; i < 4; i++) {
        int idx = tid + i * 256;
        wrow[i] = idx >> 3;
        wch[i]  = idx & 7;
    }

    float vsacc[2] = {0.0f, 0.0f};
    float xsum = 0.0f;

    uint4 pX[2], pW[4];
    auto load_regs = [&](int kk) {
        #pragma unroll
        for (int i = 0; i < 2; i++) {
            const float* sx = &X[(size_t)(r0 + xrow[i]) * SRC + kk + xch[i] * 8];
            float4 a = *reinterpret_cast<const float4*>(sx);
            float4 b = *reinterpret_cast<const float4*>(sx + 4);
            if (!isQ) {
                const float* wv = &wvs[kk + xch[i] * 8];
                vsacc[i] = fmaf(a.x, wv[0], vsacc[i]);
                vsacc[i] = fmaf(a.y, wv[1], vsacc[i]);
                vsacc[i] = fmaf(a.z, wv[2], vsacc[i]);
                vsacc[i] = fmaf(a.w, wv[3], vsacc[i]);
                vsacc[i] = fmaf(b.x, wv[4], vsacc[i]);
                vsacc[i] = fmaf(b.y, wv[5], vsacc[i]);
                vsacc[i] = fmaf(b.z, wv[6], vsacc[i]);
                vsacc[i] = fmaf(b.w, wv[7], vsacc[i]);
                xsum += (a.x + a.y) + (a.z + a.w) + (b.x + b.y) + (b.z + b.w);
            }
            pX[i] = cvt8h(a, b);
        }
        #pragma unroll
        for (int i = 0; i < 4; i++) {
            const float* sw = &W[(size_t)wrow[i] * SRC + kk + wch[i] * 8];
            pW[i] = cvt8h(*reinterpret_cast<const float4*>(sw),
                          *reinterpret_cast<const float4*>(sw + 4));
        }
    };
    auto store_smem = [&](int buf) {
        char* xb = smem_raw + OFF_XS + buf * 8192;
        char* wb = smem_raw + OFF_WS + buf * 16384;
        #pragma unroll
        for (int i = 0; i < 2; i++) {
            u32 dst = (u32)(xrow[i] * 128) + (u32)((xch[i] ^ (xrow[i] & 7)) << 4);
            *reinterpret_cast<uint4*>(xb + dst) = pX[i];
        }
        #pragma unroll
        for (int i = 0; i < 4; i++) {
            u32 dst = (u32)(wrow[i] * 128) + (u32)((wch[i] ^ (wrow[i] & 7)) << 4);
            *reinterpret_cast<uint4*>(wb + dst) = pW[i];
        }
    };

    float c[2][4][4];
    #pragma unroll
    for (int mt = 0; mt < 2; mt++)
        #pragma unroll
        for (int j = 0; j < 4; j++)
            #pragma unroll
            for (int e = 0; e < 4; e++) c[mt][j][e] = 0.0f;

    const u32 sX = smem_u32(smem_raw) + OFF_XS;
    const u32 sW = smem_u32(smem_raw) + OFF_WS;
    const int rbA = qg * 32 + (lane & 7) + (lane & 8);
    const int kbitA = lane >> 4;
    const int rbB = nh * 32 + (lane & 7) + ((lane & 16) >> 1);
    const int kbitB = (lane >> 3) & 1;

    load_regs(0);
    for (int cidx = 0; cidx < PCH; cidx++) {
        const int buf = cidx & 1;
        store_smem(buf);
        __syncthreads();
        if (cidx + 1 < PCH) load_regs((cidx + 1) * 64);

        const u32 xb = sX + buf * 8192;
        const u32 wb = sW + buf * 16384;
        #pragma unroll
        for (int ks = 0; ks < 4; ks++) {
            u32 A0[4], A1[4];
            int chA = ks * 2 + kbitA;
            {
                int r = rbA;
                ldsm_x4(A0[0], A0[1], A0[2], A0[3], xb + r * 128 + ((chA ^ (r & 7)) << 4));
            }
            {
                int r = rbA + 16;
                ldsm_x4(A1[0], A1[1], A1[2], A1[3], xb + r * 128 + ((chA ^ (r & 7)) << 4));
            }
            int chB = ks * 2 + kbitB;
            #pragma unroll
            for (int nt = 0; nt < 2; nt++) {
                u32 b[4];
                int r = rbB + nt * 16;
                ldsm_x4(b[0], b[1], b[2], b[3], wb + r * 128 + ((chB ^ (r & 7)) << 4));
                mma16816(c[0][nt*2+0][0], c[0][nt*2+0][1], c[0][nt*2+0][2], c[0][nt*2+0][3],
                         A0[0], A0[1], A0[2], A0[3], b[0], b[1]);
                mma16816(c[0][nt*2+1][0], c[0][nt*2+1][1], c[0][nt*2+1][2], c[0][nt*2+1][3],
                         A0[0], A0[1], A0[2], A0[3], b[2], b[3]);
                mma16816(c[1][nt*2+0][0], c[1][nt*2+0][1], c[1][nt*2+0][2], c[1][nt*2+0][3],
                         A1[0], A1[1], A1[2], A1[3], b[0], b[1]);
                mma16816(c[1][nt*2+1][0], c[1][nt*2+1][1], c[1][nt*2+1][2], c[1][nt*2+1][3],
                         A1[0], A1[1], A1[2], A1[3], b[2], b[3]);
            }
        }
        __syncthreads();
    }

    if (!isQ) {
        #pragma unroll
        for (int m = 1; m < 8; m <<= 1) {
            vsacc[0] += __shfl_xor_sync(0xffffffffu, vsacc[0], m);
            vsacc[1] += __shfl_xor_sync(0xffffffffu, vsacc[1], m);
            xsum     += __shfl_xor_sync(0xffffffffu, xsum, m);
        }
        if ((lane & 7) == 0) {
            g_vs[r0 + xrow[0]] = vsacc[0];
            g_vs[r0 + xrow[1]] = vsacc[1];
            atomicAdd(&g_x2sum, xsum);
        }
    }

    const float scale = isQ ? CFOLD : 1.0f;
    #pragma unroll
    for (int mt = 0; mt < 2; mt++) {
        int row = r0 + qg * 32 + mt * 16 + (lane >> 2);
        #pragma unroll
        for (int j = 0; j < 4; j++) {
            int col = nh * 32 + j * 8 + (lane & 3) * 2;
            __half2 lo = __floats2half2_rn(c[mt][j][0] * scale, c[mt][j][1] * scale);
            __half2 hi = __floats2half2_rn(c[mt][j][2] * scale, c[mt][j][3] * scale);
            *reinterpret_cast<__half2*>(&Y[(size_t)row * DK + col]) = lo;
            *reinterpret_cast<__half2*>(&Y[(size_t)(row + 8) * DK + col]) = hi;
        }
    }
}

// ---------------- kernel 3: HMMA flash attention, f16 accumulators --
// CTA: 128 queries x 64-key tiles, 8 warps (warp = 32q x 32k).
// grid (64, KSPLIT). cp.async 3-stage K ring, 1 barrier/iter.
#define OFF_KS   32768         /* __half Ks[3][64][128] */
#define OFF_VSB  81920         /* float vsb[3][64] */
#define OFF_RL   82688         /* float rl[2][128] */
#define OFF_RA   83712         /* float ra[2][128] */
#define SMEM_FLASH 84736

__global__ void __launch_bounds__(256, 2) flash_kernel() {
    float* vsb = reinterpret_cast<float*>(smem_raw + OFF_VSB);
    float* rl  = reinterpret_cast<float*>(smem_raw + OFF_RL);
    float* ra  = reinterpret_cast<float*>(smem_raw + OFF_RA);

    const int tid = threadIdx.x, lane = tid & 31, w = tid >> 5;
    const int q0 = blockIdx.x * 128;
    const int k0 = blockIdx.y * (S_N / KSPLIT);
    const int kh = w >> 2;       // key half within tile (0/1)
    const int qg = w & 3;        // 32-query group
    const u32 sbase = smem_u32(smem_raw);

    const int krow = tid >> 4, kch = tid & 15;

    auto issue_tile = [&](int it) {
        const int slot = it % 3;
        const int t0 = k0 + it * 64;
        #pragma unroll
        for (int i = 0; i < 4; i++) {
            int row = krow + i * 16;
            u32 dst = sbase + OFF_KS + slot * 16384 +
                      (u32)(row * 256) + (u32)((kch ^ (row & 7)) << 4);
            cpa16(dst, g_Kf + (size_t)(t0 + row) * DK + kch * 8);
        }
        if (tid < 64)
            cpa4(sbase + OFF_VSB + slot * 256 + tid * 4, &g_vs[t0 + tid]);
        cpa_commit();
    };

    issue_tile(0);
    issue_tile(1);

    // stage Q (XOR-swizzled)
    #pragma unroll
    for (int i = 0; i < 8; i++) {
        int idx = tid + i * 256;
        int row = idx >> 4, ch = idx & 15;
        u32 dst = (u32)(row * 256) + (u32)((ch ^ (row & 7)) << 4);
        *reinterpret_cast<uint4*>(smem_raw + dst) =
            *reinterpret_cast<const uint4*>(g_Qf + (size_t)(q0 + row) * DK + ch * 8);
    }
    __syncthreads();

    // A fragments: register-resident for the whole CTA lifetime
    u32 A[2][8][4];
    {
        int rb = qg * 32 + (lane & 7) + (lane & 8);
        int kbit = lane >> 4;
        #pragma unroll
        for (int mt = 0; mt < 2; mt++) {
            int row = rb + mt * 16;
            #pragma unroll
            for (int ks = 0; ks < 8; ks++) {
                int ch = ks * 2 + kbit;
                ldsm_x4(A[mt][ks][0], A[mt][ks][1], A[mt][ks][2], A[mt][ks][3],
                        sbase + row * 256 + ((ch ^ (row & 7)) << 4));
            }
        }
    }

    const u32 sK = sbase + OFF_KS;
    const int rB0 = kh * 32 + (lane & 7) + ((lane & 16) >> 1);
    const int kbitB = (lane >> 3) & 1;

    float l_[4] = {0, 0, 0, 0}, a_[4] = {0, 0, 0, 0};

    for (int it = 0; it < NIT; it++) {
        const int slot = it % 3;
        if (it + 1 < NIT) cpa_wait<1>(); else cpa_wait<0>();
        __syncthreads();
        if (it + 2 < NIT) issue_tile(it + 2);

        // ---- QK^T on tensor cores, fp16 accumulators ----
        u32 c2[2][4][2];
        #pragma unroll
        for (int mt = 0; mt < 2; mt++)
            #pragma unroll
            for (int j = 0; j < 4; j++) {
                c2[mt][j][0] = 0u;
                c2[mt][j][1] = 0u;
            }

        const u32 kb = sK + slot * 16384;
        #pragma unroll
        for (int ks = 0; ks < 8; ks++) {
            u32 b[8];
            int ch = ks * 2 + kbitB;
            {
                int row = rB0;
                ldsm_x4(b[0], b[1], b[2], b[3],
                        kb + row * 256 + ((ch ^ (row & 7)) << 4));
            }
            {
                int row = rB0 + 16;
                ldsm_x4(b[4], b[5], b[6], b[7],
                        kb + row * 256 + ((ch ^ (row & 7)) << 4));
            }
            #pragma unroll
            for (int mt = 0; mt < 2; mt++) {
                mma16816h(c2[mt][0][0], c2[mt][0][1],
                          A[mt][ks][0], A[mt][ks][1], A[mt][ks][2], A[mt][ks][3], b[0], b[1]);
                mma16816h(c2[mt][1][0], c2[mt][1][1],
                          A[mt][ks][0], A[mt][ks][1], A[mt][ks][2], A[mt][ks][3], b[2], b[3]);
                mma16816h(c2[mt][2][0], c2[mt][2][1],
                          A[mt][ks][0], A[mt][ks][1], A[mt][ks][2], A[mt][ks][3], b[4], b[5]);
                mma16816h(c2[mt][3][0], c2[mt][3][1],
                          A[mt][ks][0], A[mt][ks][1], A[mt][ks][2], A[mt][ks][3], b[6], b[7]);
            }
        }

        // ---- softmax accumulate: p = 2^s, f16x2 fma against packed v ----
        const float* vv = vsb + slot * 64 + kh * 32 + (lane & 3) * 2;
        u32 vs2h[4];
        #pragma unroll
        for (int j = 0; j < 4; j++) {
            float2 v2 = *reinterpret_cast<const float2*>(vv + j * 8);
            __half2 h = __floats2half2_rn(v2.x, v2.y);
            vs2h[j] = *reinterpret_cast<u32*>(&h);
        }
        u32 lh2[4] = {0u, 0u, 0u, 0u};
        u32 ah2[4] = {0u, 0u, 0u, 0u};
        #pragma unroll
        for (int j = 0; j < 4; j++) {
            #pragma unroll
            for (int mt = 0; mt < 2; mt++) {
                #pragma unroll
                for (int rr = 0; rr < 2; rr++) {
                    int r = mt * 2 + rr;
                    u32 p2 = ex2h2(c2[mt][j][rr]);
                    lh2[r] = hadd2u(lh2[r], p2);
                    ah2[r] = hfma2u(p2, vs2h[j], ah2[r]);
                }
            }
        }
        #pragma unroll
        for (int r = 0; r < 4; r++) {
            __half2 lh = *reinterpret_cast<__half2*>(&lh2[r]);
            l_[r] += __low2float(lh) + __high2float(lh);
            __half2 ah = *reinterpret_cast<__half2*>(&ah2[r]);
            a_[r] += __low2float(ah) + __high2float(ah);
        }
    }

    // quad reduce (lanes sharing a row are lane^1, lane^2)
    #pragma unroll
    for (int r = 0; r < 4; r++) {
        l_[r] += __shfl_xor_sync(0xffffffffu, l_[r], 1);
        l_[r] += __shfl_xor_sync(0xffffffffu, l_[r], 2);
        a_[r] += __shfl_xor_sync(0xffffffffu, a_[r], 1);
        a_[r] += __shfl_xor_sync(0xffffffffu, a_[r], 2);
    }
    __syncthreads();
    if ((lane & 3) == 0) {
        int gid = lane >> 2;
        #pragma unroll
        for (int r = 0; r < 4; r++) {
            int mt = r >> 1, rr = r & 1;
            int qrow = qg * 32 + mt * 16 + gid + rr * 8;
            rl[kh * 128 + qrow] = l_[r];
            ra[kh * 128 + qrow] = a_[r];
        }
    }
    __syncthreads();
    if (tid < 128) {
        int r = blockIdx.y * S_N + q0 + tid;
        g_pl[r] = rl[tid] + rl[128 + tid];
        g_pa[r] = ra[tid] + ra[128 + tid];
    }
}

// ---------------- kernel 4: fused combine + gate -------------------
// Block = 8 exact rows (1536 float4), 256 threads x 6 independent float4.
// x1 loads issue BEFORE the partials barrier so the bulk DRAM traffic
// overlaps the per-row gate computation's global-latency chain.
__global__ void __launch_bounds__(256) gate_kernel(const float* __restrict__ x1,
                                                   float* __restrict__ y) {
    __shared__ float gs[8];
    const int b = blockIdx.x, tid = threadIdx.x;

    // issue the 6 independent x1 loads first
    const float4* xin = reinterpret_cast<const float4*>(x1) + (size_t)b * 1536;
    float4* yo = reinterpret_cast<float4*>(y) + (size_t)b * 1536;
    float4 v[6];
    #pragma unroll
    for (int k = 0; k < 6; k++) v[k] = xin[tid + k * 256];

    if (tid < 8) {
        int r = 8 * b + tid;
        float g = 0.0f;
        if (g_x2sum != 0.0f) {
            float L = 0.0f, A = 0.0f;
            #pragma unroll
            for (int s = 0; s < KSPLIT; s++) {
                L += g_pl[s * S_N + r];
                A += g_pa[s * S_N + r];
            }
            g = A / L;
        }
        gs[tid] = g;
    }
    __syncthreads();

    #pragma unroll
    for (int k = 0; k < 6; k++) {
        float f = 1.0f - gs[(tid + k * 256) / 192];
        v[k].x *= f; v[k].y *= f; v[k].z *= f; v[k].w *= f;
        yo[tid + k * 256] = v[k];
    }
}

// ---------------- launch ------------------------------------------
extern "C" void kernel_launch(void* const* d_in, const int* in_sizes, int n_in,
                              void* d_out, int out_size) {
    const float* x1 = (const float*)d_in[0];
    const float* x2 = (const float*)d_in[1];
    const float* wq = (const float*)d_in[2];
    const float* wk = (const float*)d_in[3];
    const float* wv = (const float*)d_in[4];
    const float* wo = (const float*)d_in[5];
    float* y = (float*)d_out;

    cudaFuncSetAttribute(flash_kernel, cudaFuncAttributeMaxDynamicSharedMemorySize,
                         SMEM_FLASH);
    cudaFuncSetAttribute(proj_kernel, cudaFuncAttributeMaxDynamicSharedMemorySize,
                         SMEM_PROJ);

    prep_kernel<<<1, 768>>>(wv, wo);
    proj_kernel<<<dim3(S_N / 64, 2), 256, SMEM_PROJ>>>(x1, x2, wq, wk);
    flash_kernel<<<dim3(S_N / 128, KSPLIT), 256, SMEM_FLASH>>>();
    gate_kernel<<<S_N / 8, 256>>>(x1, y);
}